// round 12
// baseline (speedup 1.0000x reference)
#include <cuda_runtime.h>

// WaveletMask: fused Haar fwd -> mosaic weight multiply -> Haar inv.
// H=128, HB=64. One thread per 2x2 spatial block => 4096 threads total.
// Each thread: 2x float2 loads (x), 4x float loads (weight), 2x float2 stores.
//
// FINAL configuration after 10-round sweep: 32 blocks x 128 threads.
// Problem is launch-overhead-bound (192KB total traffic, DRAM<=0.4% in every
// profile); kernel floor ~4.0us, e2e floor ~4.6us. Best measured: 3.968us /
// 4.576us with exactly this source (R1/R8).

#define H 128
#define HB 64

__global__ void __launch_bounds__(128, 1) wavelet_mask_kernel(
    const float* __restrict__ x,
    const float* __restrict__ w,
    float* __restrict__ out)
{
    const int t = blockIdx.x * blockDim.x + threadIdx.x;   // 0..4095
    const int i = t >> 6;          // block row 0..63
    const int j = t & 63;          // block col 0..63

    // Vectorized loads of the 2x2 input block
    const float2 top = *reinterpret_cast<const float2*>(x + (2 * i) * H + 2 * j);
    const float2 bot = *reinterpret_cast<const float2*>(x + (2 * i + 1) * H + 2 * j);
    const float a = top.x, b = top.y, c = bot.x, d = bot.y;

    // Mosaic weights: LL / LH / HL / HH quadrants
    const float wll = w[i * H + j];
    const float wlh = w[i * H + j + HB];
    const float whl = w[(i + HB) * H + j];
    const float whh = w[(i + HB) * H + j + HB];

    // Forward Haar (orthonormal) * weight
    const float apb = a + b, amb = a - b, cpd = c + d, cmd = c - d;
    const float ll = (apb + cpd) * 0.5f * wll;
    const float lh = (apb - cpd) * 0.5f * wlh;
    const float hl = (amb + cmd) * 0.5f * whl;
    const float hh = (amb - cmd) * 0.5f * whh;

    // Inverse Haar
    const float lplh = ll + lh, lmlh = ll - lh;
    const float hphh = hl + hh, hmhh = hl - hh;
    float2 otop, obot;
    otop.x = (lplh + hphh) * 0.5f;   // a'
    otop.y = (lplh - hphh) * 0.5f;   // b'
    obot.x = (lmlh + hmhh) * 0.5f;   // c'
    obot.y = (lmlh - hmhh) * 0.5f;   // d'

    *reinterpret_cast<float2*>(out + (2 * i) * H + 2 * j)     = otop;
    *reinterpret_cast<float2*>(out + (2 * i + 1) * H + 2 * j) = obot;
}

extern "C" void kernel_launch(void* const* d_in, const int* in_sizes, int n_in,
                              void* d_out, int out_size)
{
    const float* x = (const float*)d_in[0];
    const float* w = (const float*)d_in[1];
    float* out = (float*)d_out;
    // 4096 threads total: 32 blocks x 128 threads, spread across SMs
    wavelet_mask_kernel<<<32, 128>>>(x, w, out);
}

// round 13
// speedup vs baseline: 1.0847x; 1.0847x over previous
#include <cuda_runtime.h>

// WaveletMask: fused Haar fwd -> mosaic weight multiply -> Haar inv.
// H=128, HB=64. One thread per 2x2 spatial block => 4096 threads total.
// Each thread: 2x float2 loads (x), 4x float loads (weight), 2x float2 stores.
//
// FINAL configuration (11-round sweep complete): 32 blocks x 128 threads.
// Kernel time is deterministic at the launch floor: 3.968-4.000us in every
// profile of this geometry. e2e varies 4.576-6.1us purely from harness/replay
// noise with bit-identical SASS. Problem is launch-overhead-bound: 192KB
// total traffic (~24ns at HBM spec), DRAM/L2/pipe <=0.4% in all profiles.

#define H 128
#define HB 64

__global__ void __launch_bounds__(128, 1) wavelet_mask_kernel(
    const float* __restrict__ x,
    const float* __restrict__ w,
    float* __restrict__ out)
{
    const int t = blockIdx.x * blockDim.x + threadIdx.x;   // 0..4095
    const int i = t >> 6;          // block row 0..63
    const int j = t & 63;          // block col 0..63

    // Vectorized loads of the 2x2 input block
    const float2 top = *reinterpret_cast<const float2*>(x + (2 * i) * H + 2 * j);
    const float2 bot = *reinterpret_cast<const float2*>(x + (2 * i + 1) * H + 2 * j);
    const float a = top.x, b = top.y, c = bot.x, d = bot.y;

    // Mosaic weights: LL / LH / HL / HH quadrants
    const float wll = w[i * H + j];
    const float wlh = w[i * H + j + HB];
    const float whl = w[(i + HB) * H + j];
    const float whh = w[(i + HB) * H + j + HB];

    // Forward Haar (orthonormal) * weight
    const float apb = a + b, amb = a - b, cpd = c + d, cmd = c - d;
    const float ll = (apb + cpd) * 0.5f * wll;
    const float lh = (apb - cpd) * 0.5f * wlh;
    const float hl = (amb + cmd) * 0.5f * whl;
    const float hh = (amb - cmd) * 0.5f * whh;

    // Inverse Haar
    const float lplh = ll + lh, lmlh = ll - lh;
    const float hphh = hl + hh, hmhh = hl - hh;
    float2 otop, obot;
    otop.x = (lplh + hphh) * 0.5f;   // a'
    otop.y = (lplh - hphh) * 0.5f;   // b'
    obot.x = (lmlh + hmhh) * 0.5f;   // c'
    obot.y = (lmlh - hmhh) * 0.5f;   // d'

    *reinterpret_cast<float2*>(out + (2 * i) * H + 2 * j)     = otop;
    *reinterpret_cast<float2*>(out + (2 * i + 1) * H + 2 * j) = obot;
}

extern "C" void kernel_launch(void* const* d_in, const int* in_sizes, int n_in,
                              void* d_out, int out_size)
{
    const float* x = (const float*)d_in[0];
    const float* w = (const float*)d_in[1];
    float* out = (float*)d_out;
    // 4096 threads total: 32 blocks x 128 threads, spread across SMs
    wavelet_mask_kernel<<<32, 128>>>(x, w, out);
}

// round 14
// speedup vs baseline: 1.2308x; 1.1346x over previous
#include <cuda_runtime.h>

// WaveletMask: fused Haar fwd -> mosaic weight multiply -> Haar inv.
// H=128, HB=64. One thread per 2x2 spatial block => 4096 threads total.
// Each thread: 2x float2 loads (x), 4x float loads (weight), 2x float2 stores.
//
// FINAL configuration (12-round sweep complete): 32 blocks x 128 threads.
// The kernel is at the launch-overhead floor: 192KB total traffic (~24ns of
// HBM time) against ~4us of launch/ramp cost; DRAM/L2/pipe <=0.4% in every
// profile. Bit-identical binaries measured kernel 3.968-4.768us and e2e
// 4.576-6.144us across runs -> residual variance is container clock/DVFS
// state, not code. Best recorded e2e with this exact source: 4.576us.

#define H 128
#define HB 64

__global__ void __launch_bounds__(128, 1) wavelet_mask_kernel(
    const float* __restrict__ x,
    const float* __restrict__ w,
    float* __restrict__ out)
{
    const int t = blockIdx.x * blockDim.x + threadIdx.x;   // 0..4095
    const int i = t >> 6;          // block row 0..63
    const int j = t & 63;          // block col 0..63

    // Vectorized loads of the 2x2 input block
    const float2 top = *reinterpret_cast<const float2*>(x + (2 * i) * H + 2 * j);
    const float2 bot = *reinterpret_cast<const float2*>(x + (2 * i + 1) * H + 2 * j);
    const float a = top.x, b = top.y, c = bot.x, d = bot.y;

    // Mosaic weights: LL / LH / HL / HH quadrants
    const float wll = w[i * H + j];
    const float wlh = w[i * H + j + HB];
    const float whl = w[(i + HB) * H + j];
    const float whh = w[(i + HB) * H + j + HB];

    // Forward Haar (orthonormal) * weight
    const float apb = a + b, amb = a - b, cpd = c + d, cmd = c - d;
    const float ll = (apb + cpd) * 0.5f * wll;
    const float lh = (apb - cpd) * 0.5f * wlh;
    const float hl = (amb + cmd) * 0.5f * whl;
    const float hh = (amb - cmd) * 0.5f * whh;

    // Inverse Haar
    const float lplh = ll + lh, lmlh = ll - lh;
    const float hphh = hl + hh, hmhh = hl - hh;
    float2 otop, obot;
    otop.x = (lplh + hphh) * 0.5f;   // a'
    otop.y = (lplh - hphh) * 0.5f;   // b'
    obot.x = (lmlh + hmhh) * 0.5f;   // c'
    obot.y = (lmlh - hmhh) * 0.5f;   // d'

    *reinterpret_cast<float2*>(out + (2 * i) * H + 2 * j)     = otop;
    *reinterpret_cast<float2*>(out + (2 * i + 1) * H + 2 * j) = obot;
}

extern "C" void kernel_launch(void* const* d_in, const int* in_sizes, int n_in,
                              void* d_out, int out_size)
{
    const float* x = (const float*)d_in[0];
    const float* w = (const float*)d_in[1];
    float* out = (float*)d_out;
    // 4096 threads total: 32 blocks x 128 threads, spread across SMs
    wavelet_mask_kernel<<<32, 128>>>(x, w, out);
}

// round 15
// speedup vs baseline: 1.3333x; 1.0833x over previous
#include <cuda_runtime.h>

// WaveletMask: fused Haar fwd -> mosaic weight multiply -> Haar inv.
// H=128, HB=64. One thread per 2x2 spatial block => 4096 threads total.
// Each thread: 2x float2 loads (x), 4x float loads (weight), 2x float2 stores.
//
// FINAL configuration (13-round sweep complete): 32 blocks x 128 threads.
// Launch-overhead-bound: 192KB total traffic (~24ns of HBM time) vs ~4us
// launch/ramp floor; DRAM/L2/pipe <=0.4% in every profile of every variant.
// This exact binary measured kernel 3.968/3.968/4.768/4.000us and e2e
// 4.576/6.144/5.664/4.992us across four runs -> kernel deterministic at the
// floor, e2e variance is container clock/DVFS + harness replay state.
// Holding the best-known configuration; no code-side lever remains.

#define H 128
#define HB 64

__global__ void __launch_bounds__(128, 1) wavelet_mask_kernel(
    const float* __restrict__ x,
    const float* __restrict__ w,
    float* __restrict__ out)
{
    const int t = blockIdx.x * blockDim.x + threadIdx.x;   // 0..4095
    const int i = t >> 6;          // block row 0..63
    const int j = t & 63;          // block col 0..63

    // Vectorized loads of the 2x2 input block
    const float2 top = *reinterpret_cast<const float2*>(x + (2 * i) * H + 2 * j);
    const float2 bot = *reinterpret_cast<const float2*>(x + (2 * i + 1) * H + 2 * j);
    const float a = top.x, b = top.y, c = bot.x, d = bot.y;

    // Mosaic weights: LL / LH / HL / HH quadrants
    const float wll = w[i * H + j];
    const float wlh = w[i * H + j + HB];
    const float whl = w[(i + HB) * H + j];
    const float whh = w[(i + HB) * H + j + HB];

    // Forward Haar (orthonormal) * weight
    const float apb = a + b, amb = a - b, cpd = c + d, cmd = c - d;
    const float ll = (apb + cpd) * 0.5f * wll;
    const float lh = (apb - cpd) * 0.5f * wlh;
    const float hl = (amb + cmd) * 0.5f * whl;
    const float hh = (amb - cmd) * 0.5f * whh;

    // Inverse Haar
    const float lplh = ll + lh, lmlh = ll - lh;
    const float hphh = hl + hh, hmhh = hl - hh;
    float2 otop, obot;
    otop.x = (lplh + hphh) * 0.5f;   // a'
    otop.y = (lplh - hphh) * 0.5f;   // b'
    obot.x = (lmlh + hmhh) * 0.5f;   // c'
    obot.y = (lmlh - hmhh) * 0.5f;   // d'

    *reinterpret_cast<float2*>(out + (2 * i) * H + 2 * j)     = otop;
    *reinterpret_cast<float2*>(out + (2 * i + 1) * H + 2 * j) = obot;
}

extern "C" void kernel_launch(void* const* d_in, const int* in_sizes, int n_in,
                              void* d_out, int out_size)
{
    const float* x = (const float*)d_in[0];
    const float* w = (const float*)d_in[1];
    float* out = (float*)d_out;
    // 4096 threads total: 32 blocks x 128 threads, spread across SMs
    wavelet_mask_kernel<<<32, 128>>>(x, w, out);
}